// round 17
// baseline (speedup 1.0000x reference)
#include <cuda_runtime.h>
#include <cuda_bf16.h>

#define NN 50000
#define EE 800000
#define IC  128
#define OC  64
#define TILES ((NN + 63) / 64)        // 782 gemm tiles
#define BUILD_BLOCKS 112
#define GRID 444                      // 148 * 3 -> one resident wave
#define SCAN_BLOCKS 98                // 98 * 512 >= NN

// ---- scratch (no device allocations; zero-initialized at module load) ----
__device__ __align__(16) float g_h[NN * OC];
__device__ float g_adst[NN];
__device__ float g_asrc[NN];
__device__ int   g_deg[NN];       // zeros on entry; restored during scan
__device__ int   g_ptr[NN + 1];
__device__ int   g_cursor[NN];
__device__ int   g_col[EE];
__device__ int   g_agg[128];
__device__ int   g_barcnt[3];     // monotonic barrier counters (never reset)
__device__ int   g_tile;          // GEMM tile-steal counter (reset by k6)

// int64-layout sniff: ids < 2^31 => odd 32-bit words all zero
__device__ __forceinline__ bool sniff64(const int* ei32) {
    int z = (ei32[1] == 0) + (ei32[3] == 0) + (ei32[5] == 0) +
            (ei32[7] == 0) + (ei32[9] == 0) + (ei32[11] == 0);
    return z == 6;
}

// monotonic spin barrier among `span` resident blocks: no reset needed.
// target = next multiple of span above my arrival index.
__device__ __forceinline__ void span_barrier(int id, int span) {
    __syncthreads();
    if (threadIdx.x == 0) {
        __threadfence();
        int prev = atomicAdd(&g_barcnt[id], 1);
        int target = prev - (prev % span) + span;
        while (atomicAdd(&g_barcnt[id], 0) < target) { }
        __threadfence();
    }
    __syncthreads();
}

// packed fp32x2 FMA: d = a * b + d  (sm_100+)
__device__ __forceinline__ void ffma2(unsigned long long& d,
                                      unsigned long long a,
                                      unsigned long long b) {
    asm("fma.rn.f32x2 %0, %1, %2, %0;" : "+l"(d) : "l"(a), "l"(b));
}
__device__ __forceinline__ unsigned long long dup2(float v) {
    unsigned long long p;
    unsigned int b = __float_as_uint(v);
    asm("mov.b64 %0, {%1, %2};" : "=l"(p) : "r"(b), "r"(b));
    return p;
}
__device__ __forceinline__ float2 unpack2(unsigned long long p) {
    unsigned int lo, hi;
    asm("mov.b64 {%0, %1}, %2;" : "=r"(lo), "=r"(hi) : "l"(p));
    return make_float2(__uint_as_float(lo), __uint_as_float(hi));
}

// ============================================================
// MEGA: blocks [0,112) build CSR then join the GEMM tile pool;
// blocks [112,444) steal GEMM tiles from the start.
// GEMM: h = x@W + fused attention dots, f32x2-packed FMAs.
// ============================================================
__global__ __launch_bounds__(256, 3) void mega(
    const float* __restrict__ x, const float* __restrict__ W,
    const float* __restrict__ att, const int* __restrict__ ei32)
{
    __shared__ float Ws[64][64];
    __shared__ float Xs[64][68];
    __shared__ int   ish[128];
    __shared__ int   tsh;
    const int tid = threadIdx.x;
    const int bid = blockIdx.x;

    if (bid < BUILD_BLOCKS) {
        // ---------------- build role ----------------
        const bool is64 = sniff64(ei32);

        // Phase A: in-degree histogram
        for (int e = bid * 256 + tid; e < EE; e += BUILD_BLOCKS * 256) {
            int d = is64 ? ei32[2 * (EE + e)] : ei32[EE + e];
            d = min(max(d, 0), NN - 1);
            atomicAdd(&g_deg[d], 1);
        }
        span_barrier(0, BUILD_BLOCKS);

        // Phase B1: local exclusive scan (blocks 0..97, 512 elems each)
        int v0 = 0, v1 = 0, local_excl = 0;
        int i0 = 0, i1 = 0;
        if (bid < SCAN_BLOCKS) {
            const int lane = tid & 31, wid = tid >> 5;
            i0 = bid * 512 + 2 * tid;
            i1 = i0 + 1;
            v0 = (i0 < NN) ? g_deg[i0] : 0;
            v1 = (i1 < NN) ? g_deg[i1] : 0;
            if (i0 < NN) g_deg[i0] = 0;    // restore invariant
            if (i1 < NN) g_deg[i1] = 0;
            int ts = v0 + v1, s = ts;
#pragma unroll
            for (int o = 1; o < 32; o <<= 1) {
                int t = __shfl_up_sync(0xffffffffu, s, o);
                if (lane >= o) s += t;
            }
            if (lane == 31) ish[wid] = s;
            __syncthreads();
            if (wid == 0 && lane < 8) {
                int ws = ish[lane];
#pragma unroll
                for (int o = 1; o < 8; o <<= 1) {
                    int t = __shfl_up_sync(0x000000ffu, ws, o);
                    if (lane >= o) ws += t;
                }
                ish[lane] = ws;
            }
            __syncthreads();
            local_excl = (s - ts) + ((wid > 0) ? ish[wid - 1] : 0);
            if (tid == 0) g_agg[bid] = ish[7];   // single writer
            __syncthreads();
        }
        span_barrier(1, BUILD_BLOCKS);

        // Phase B2: cross-block prefix + write ptr/cursor
        if (bid < SCAN_BLOCKS) {
            if (tid < 128) ish[tid] = (tid < bid) ? g_agg[tid] : 0;
            __syncthreads();
#pragma unroll
            for (int o = 64; o > 0; o >>= 1) {
                if (tid < o) ish[tid] += ish[tid + o];
                __syncthreads();
            }
            const int prefix = ish[0];
            int e0 = prefix + local_excl;
            if (i0 < NN) { g_ptr[i0] = e0;      g_cursor[i0] = e0; }
            if (i1 < NN) { g_ptr[i1] = e0 + v0; g_cursor[i1] = e0 + v0; }
            if (bid == 0 && tid == 0) g_ptr[NN] = EE;
        }
        span_barrier(2, BUILD_BLOCKS);

        // Phase C: fill CSR columns
        for (int e = bid * 256 + tid; e < EE; e += BUILD_BLOCKS * 256) {
            int s, d;
            if (is64) { s = ei32[2 * e]; d = ei32[2 * (EE + e)]; }
            else      { s = ei32[e];     d = ei32[EE + e]; }
            s = min(max(s, 0), NN - 1);
            d = min(max(d, 0), NN - 1);
            int pos = atomicAdd(&g_cursor[d], 1);
            g_col[pos] = s;
        }
        __syncthreads();
        // fall through to the tile pool
    }

    // ---------------- gemm role (all blocks; work-stealing) ----------------
    const int tx = tid & 15;
    const int ty = tid >> 4;

    float att_d[4], att_s[4];
#pragma unroll
    for (int j = 0; j < 4; j++) {
        att_d[j] = att[tx * 4 + j];
        att_s[j] = att[64 + tx * 4 + j];
    }

    const int fk = tid >> 4;            // k row group
    const int fc = (tid & 15) * 4;      // 4 consecutive columns / k's

    for (;;) {
        if (tid == 0) tsh = atomicAdd(&g_tile, 1);
        __syncthreads();
        const int tile = tsh;
        if (tile >= TILES) break;

        const int n0 = tile * 64;
        unsigned long long accp[4][2];
#pragma unroll
        for (int i = 0; i < 4; i++) { accp[i][0] = 0ull; accp[i][1] = 0ull; }

        for (int kc = 0; kc < IC; kc += 64) {
#pragma unroll
            for (int kk = 0; kk < 64; kk += 16) {
                int k = fk + kk;
                *(float4*)&Ws[k][fc] = *(const float4*)&W[(kc + k) * OC + fc];
            }
#pragma unroll
            for (int kk = 0; kk < 64; kk += 16) {
                int r = fk + kk;
                int n = n0 + r;
                float4 xv = (n < NN) ? *(const float4*)&x[n * IC + kc + fc]
                                     : make_float4(0.f, 0.f, 0.f, 0.f);
                Xs[fc + 0][r] = xv.x;
                Xs[fc + 1][r] = xv.y;
                Xs[fc + 2][r] = xv.z;
                Xs[fc + 3][r] = xv.w;
            }
            __syncthreads();
#pragma unroll
            for (int k = 0; k < 64; k++) {
                float4 xv = *(const float4*)&Xs[k][ty * 4];
                const unsigned long long* wp =
                    (const unsigned long long*)&Ws[k][tx * 4];
                unsigned long long w0 = wp[0], w1 = wp[1];
                unsigned long long x0 = dup2(xv.x);
                unsigned long long x1 = dup2(xv.y);
                unsigned long long x2 = dup2(xv.z);
                unsigned long long x3 = dup2(xv.w);
                ffma2(accp[0][0], x0, w0); ffma2(accp[0][1], x0, w1);
                ffma2(accp[1][0], x1, w0); ffma2(accp[1][1], x1, w1);
                ffma2(accp[2][0], x2, w0); ffma2(accp[2][1], x2, w1);
                ffma2(accp[3][0], x3, w0); ffma2(accp[3][1], x3, w1);
            }
            __syncthreads();
        }

#pragma unroll
        for (int i = 0; i < 4; i++) {
            float2 p0 = unpack2(accp[i][0]);
            float2 p1 = unpack2(accp[i][1]);
            int n = n0 + ty * 4 + i;
            if (n < NN) {
                float4 v = make_float4(p0.x, p0.y, p1.x, p1.y);
                *(float4*)(g_h + n * OC + tx * 4) = v;
            }
            float pd = p0.x * att_d[0] + p0.y * att_d[1] +
                       p1.x * att_d[2] + p1.y * att_d[3];
            float ps = p0.x * att_s[0] + p0.y * att_s[1] +
                       p1.x * att_s[2] + p1.y * att_s[3];
#pragma unroll
            for (int o = 8; o > 0; o >>= 1) {
                pd += __shfl_down_sync(0xffffffffu, pd, o, 16);
                ps += __shfl_down_sync(0xffffffffu, ps, o, 16);
            }
            if (tx == 0 && n < NN) {
                g_adst[n] = pd;
                g_asrc[n] = ps;
            }
        }
        __syncthreads();   // protect tsh/Xs before next steal
    }
}

// ============================================================
// K6: fused gather + softmax + bias + L2 norm.
// One node per half-warp; 16-edge chunks staged in smem;
// hot loop unroll x4 (MLP 4). Resets g_tile for next replay.
// ============================================================
__global__ void k6_gather(const float* __restrict__ bias, float* __restrict__ out) {
    __shared__ float2 stage[8][32];
    if (blockIdx.x == 0 && threadIdx.x == 0) g_tile = 0;
    const int tid = threadIdx.x;
    const int lane = tid & 31;
    const int wwid = tid >> 5;
    const int hw  = lane >> 4;                 // which half
    const int lil = lane & 15;                 // lane in half = float4 col group
    const unsigned hm = hw ? 0xFFFF0000u : 0x0000FFFFu;
    const int n = blockIdx.x * 16 + wwid * 2 + hw;   // NN = 3125*16 exactly

    const float ad = g_adst[n];

    // self loop (all 16 lanes of this half active)
    float al = ad + g_asrc[n];
    al = (al > 0.f) ? al : 0.2f * al;
    float wself = __expf(al);
    float4 hv = *(const float4*)(g_h + n * OC + lil * 4);
    float4 acc;
    acc.x = wself * hv.x; acc.y = wself * hv.y;
    acc.z = wself * hv.z; acc.w = wself * hv.w;

    float wlane = 0.f;

    const int beg = g_ptr[n];
    const int end = g_ptr[n + 1];
    const float2* st = &stage[wwid][hw * 16];
    for (int base = beg; base < end; base += 16) {
        const int idx = base + lil;
        int sO = 0;
        float w = 0.f;
        if (idx < end) {
            int s = g_col[idx];                // 64B contiguous per half
            float a = ad + g_asrc[s];
            a = (a > 0.f) ? a : 0.2f * a;
            w = __expf(a);
            sO = s * OC;                       // premultiplied row offset
        }
        wlane += w;
        stage[wwid][lane] = make_float2(__int_as_float(sO), w);
        __syncwarp(hm);

        const int cnt = min(16, end - base);
        const int pr = (cnt + 3) & ~3;         // <=16
        for (int j = 0; j < pr; j += 4) {
            float2 e0 = st[j];
            float2 e1 = st[j + 1];
            float2 e2 = st[j + 2];
            float2 e3 = st[j + 3];
            int s0 = __float_as_int(e0.x);
            int s1 = __float_as_int(e1.x);
            int s2 = __float_as_int(e2.x);
            int s3 = __float_as_int(e3.x);
            float4 h0 = *(const float4*)(g_h + s0 + lil * 4);
            float4 h1 = *(const float4*)(g_h + s1 + lil * 4);
            float4 h2 = *(const float4*)(g_h + s2 + lil * 4);
            float4 h3 = *(const float4*)(g_h + s3 + lil * 4);
            acc.x += e0.y * h0.x; acc.y += e0.y * h0.y;
            acc.z += e0.y * h0.z; acc.w += e0.y * h0.w;
            acc.x += e1.y * h1.x; acc.y += e1.y * h1.y;
            acc.z += e1.y * h1.z; acc.w += e1.y * h1.w;
            acc.x += e2.y * h2.x; acc.y += e2.y * h2.y;
            acc.z += e2.y * h2.z; acc.w += e2.y * h2.w;
            acc.x += e3.y * h3.x; acc.y += e3.y * h3.y;
            acc.z += e3.y * h3.z; acc.w += e3.y * h3.w;
        }
        __syncwarp(hm);   // protect stage before next chunk overwrites
    }

    // weight-sum reduce within the half
    float wsum = wlane;
#pragma unroll
    for (int o = 8; o > 0; o >>= 1) wsum += __shfl_xor_sync(hm, wsum, o);
    wsum += wself;

    const float4 bv = *(const float4*)(bias + lil * 4);
    float inv_s = 1.0f / (wsum + 1e-16f);
    float v0 = acc.x * inv_s + bv.x;
    float v1 = acc.y * inv_s + bv.y;
    float v2 = acc.z * inv_s + bv.z;
    float v3 = acc.w * inv_s + bv.w;

    // L2 norm over the 16 lanes of the half
    float ss = v0 * v0 + v1 * v1 + v2 * v2 + v3 * v3;
#pragma unroll
    for (int o = 8; o > 0; o >>= 1) ss += __shfl_xor_sync(hm, ss, o);
    float inv = 1.0f / fmaxf(sqrtf(ss), 1e-12f);
    *(float4*)(out + n * OC + lil * 4) =
        make_float4(v0 * inv, v1 * inv, v2 * inv, v3 * inv);
}

extern "C" void kernel_launch(void* const* d_in, const int* in_sizes, int n_in,
                              void* d_out, int out_size) {
    const float* x = (const float*)d_in[0];
    const int* ei32 = (const int*)d_in[1];   // dtype sniffed on device
    const float* W = (const float*)d_in[2];
    const float* att = (const float*)d_in[3];
    const float* bias = (const float*)d_in[4];
    float* out = (float*)d_out;

    mega<<<GRID, 256>>>(x, W, att, ei32);
    k6_gather<<<NN / 16, 256>>>(bias, out);
}